// round 7
// baseline (speedup 1.0000x reference)
#include <cuda_runtime.h>

#define BATCH  2
#define NV     4096
#define NF     4096
#define IMG_H  256
#define IMG_W  256
#define ROWS_PB 4
#define THREADS (IMG_W * ROWS_PB)   // 1024

// ---------------------------------------------------------------------------
// Block = 4 image rows (1024 px / 1024 threads), grid = 128 (single wave).
// Phase 1: transform ALL 4096 vertices of this batch into smem (4 per thread,
//          fully coalesced, no index-dependent load chain).
// Phase 2: barrier-free per-pixel triangle scan with early exit. Face indices
//          are warp-uniform __ldg broadcasts; vertices come from smem.
// Vertex transform and edge-function expression order are bit-identical to
// all previous passing rounds (rel_err == 0).
// ---------------------------------------------------------------------------
__global__ void __launch_bounds__(THREADS) raster_block(
    const float* __restrict__ verts,   // [B,NV,3]
    const int*   __restrict__ faces,   // [B,NF,3]
    const float* __restrict__ Rm,      // [B,3,3]
    const float* __restrict__ Tm,      // [B,3]
    float*       __restrict__ out)     // [B,H,W,3]
{
    __shared__ float2 sxy[NV];         // all transformed ndc (x,y), 32 KB

    const int rowsPerBatch = IMG_H / ROWS_PB;     // 64 blocks per batch
    int b  = blockIdx.x / rowsPerBatch;
    int y0 = (blockIdx.x - b * rowsPerBatch) * ROWS_PB;
    int x  = threadIdx.x & (IMG_W - 1);
    int y  = y0 + (threadIdx.x >> 8);

    const int*   fb = faces + b * NF * 3;
    const float* vb = verts + b * NV * 3;

    // ---- issue the 4 vertex loads FIRST (independent of R/T loads) ----
    float vx[4], vy[4], vz[4];
    #pragma unroll
    for (int k = 0; k < 4; ++k) {
        int v = threadIdx.x + k * THREADS;
        vx[k] = __ldg(&vb[v * 3 + 0]);
        vy[k] = __ldg(&vb[v * 3 + 1]);
        vz[k] = __ldg(&vb[v * 3 + 2]);
    }

    // pixel center in ndc (same expression order as reference)
    float px = (((float)x + 0.5f) / (float)IMG_W) * 2.0f - 1.0f;
    float py = (((float)y + 0.5f) / (float)IMG_H) * 2.0f - 1.0f;

    // ---- VP rows for this batch (uniform loads; identical ordering) ----
    const float* R = Rm + b * 9;
    const float* T = Tm + b * 3;

    float t0 = -((R[0] * T[0] + R[3] * T[1]) + R[6] * T[2]);
    float t1 = -((R[1] * T[0] + R[4] * T[1]) + R[7] * T[2]);
    float t2 = -((R[2] * T[0] + R[5] * T[1]) + R[8] * T[2]);

    const float f = 1.7320508075688772f;   // 1/tan(30 deg)

    float VP00 = f * R[0], VP01 = f * R[3], VP02 = f * R[6], VP03 = f * t0;
    float VP10 = f * R[1], VP11 = f * R[4], VP12 = f * R[7], VP13 = f * t1;
    float VP30 = -R[2],    VP31 = -R[5],    VP32 = -R[8],    VP33 = -t2;

    // ---- transform the 4 vertices, store to smem ----
    #pragma unroll
    for (int k = 0; k < 4; ++k) {
        int v = threadIdx.x + k * THREADS;
        float cx = ((vx[k] * VP00 + vy[k] * VP01) + vz[k] * VP02) + VP03;
        float cy = ((vx[k] * VP10 + vy[k] * VP11) + vz[k] * VP12) + VP13;
        float cw = ((vx[k] * VP30 + vy[k] * VP31) + vz[k] * VP32) + VP33;
        float w  = fmaxf(cw, 1e-8f);
        sxy[v] = make_float2(cx / w, cy / w);
    }
    __syncthreads();

    // inside-test for triangle t (expression order matches reference)
    auto tri_inside = [&](int t) -> bool {
        int i0 = __ldg(&fb[t * 3 + 0]);   // warp-uniform -> L1 broadcast
        int i1 = __ldg(&fb[t * 3 + 1]);
        int i2 = __ldg(&fb[t * 3 + 2]);
        float2 p0 = sxy[i0];
        float2 p1 = sxy[i1];
        float2 p2 = sxy[i2];
        float e0 = (p1.x - p0.x) * (py - p0.y) - (p1.y - p0.y) * (px - p0.x);
        float e1 = (p2.x - p1.x) * (py - p1.y) - (p2.y - p1.y) * (px - p1.x);
        float e2 = (p0.x - p2.x) * (py - p2.y) - (p0.y - p2.y) * (px - p2.x);
        bool pos = (e0 >= 0.0f) & (e1 >= 0.0f) & (e2 >= 0.0f);
        bool neg = (e0 <= 0.0f) & (e1 <= 0.0f) & (e2 <= 0.0f);
        return pos | neg;
    };

    // ---- barrier-free scan, 4 triangles per iteration (OR is order-free) --
    float covered = 0.0f;
    for (int t = 0; t < NF; t += 4) {
        bool hit = tri_inside(t)     | tri_inside(t + 1)
                 | tri_inside(t + 2) | tri_inside(t + 3);
        if (hit) { covered = 1.0f; break; }
    }

    int pix = (b * IMG_H + y) * IMG_W + x;
    float* o = out + (size_t)pix * 3;
    o[0] = covered;
    o[1] = covered;
    o[2] = covered;
}

// ---------------------------------------------------------------------------
extern "C" void kernel_launch(void* const* d_in, const int* in_sizes, int n_in,
                              void* d_out, int out_size) {
    const float* verts = (const float*)d_in[0];   // [2,4096,3]
    const int*   faces = (const int*)  d_in[1];   // [2,4096,3]
    const float* Rm    = (const float*)d_in[2];   // [2,3,3]
    const float* Tm    = (const float*)d_in[3];   // [2,3]
    float* out = (float*)d_out;                   // [2,256,256,3]

    raster_block<<<BATCH * (IMG_H / ROWS_PB), THREADS>>>(verts, faces, Rm, Tm, out);
}